// round 3
// baseline (speedup 1.0000x reference)
#include <cuda_runtime.h>

#define R_BINS 64
#define Z_BINS 64
#define NBINS (R_BINS * Z_BINS)
#define NBLOCKS (148 * 3)
#define NTHREADS 512

__device__ float g_hist[NBINS];          // zero at module load; kernel leaves it zeroed
__device__ unsigned int g_ticket;        // zero at module load; kernel resets it

// Swizzled shared index: bank = (j ^ (i&63)) % 32 decorrelates the z-hot banks.
static __device__ __forceinline__ void bin_point(float* sh, float x, float y, float z, float m) {
    const float DRf = 0.15625f;          // exact in fp32
    const float INV_DR = 6.4f;           // inexact; fixed up against exact edges
    const float Z_MINf = -2.0f;
    const float INV_DZ = 16.0f;          // exact, multiply == reference divide
    float r = sqrtf(x * x + y * y);
    int i = (int)(r * INV_DR);           // r >= 0 -> trunc == floor
    if (r < (float)i * DRf) --i;
    else if (r >= (float)(i + 1) * DRf) ++i;
    int j = (int)floorf((z - Z_MINf) * INV_DZ);
    if (i >= 0 && i < R_BINS && j >= 0 && j < Z_BINS) {
        atomicAdd(sh + (i << 6) + (j ^ (i & 63)), m);
    }
}

static __device__ __forceinline__ void bin_group(float* sh, float4 a, float4 b, float4 c, float4 m) {
    bin_point(sh, a.x, a.y, a.z, m.x);
    bin_point(sh, a.w, b.x, b.y, m.y);
    bin_point(sh, b.z, b.w, c.x, m.z);
    bin_point(sh, c.y, c.z, c.w, m.w);
}

__global__ void __launch_bounds__(NTHREADS, 3)
fused_hist_kernel(const float4* __restrict__ pos4,
                  const float4* __restrict__ mass4,
                  int ngroups,
                  float* __restrict__ out) {
    __shared__ float sh[NBINS];
    __shared__ int s_is_last;
    for (int i = threadIdx.x; i < NBINS; i += NTHREADS) sh[i] = 0.0f;
    __syncthreads();

    const int stride = gridDim.x * NTHREADS;
    int g = blockIdx.x * NTHREADS + threadIdx.x;

    // Unroll-by-2: 8 coalesced LDG.128 batched before any atomics (MLP_p1 = 8).
    for (; g + stride < ngroups; g += 2 * stride) {
        int h = g + stride;
        float4 a1 = pos4[3 * g + 0];
        float4 b1 = pos4[3 * g + 1];
        float4 c1 = pos4[3 * g + 2];
        float4 m1 = mass4[g];
        float4 a2 = pos4[3 * h + 0];
        float4 b2 = pos4[3 * h + 1];
        float4 c2 = pos4[3 * h + 2];
        float4 m2 = mass4[h];
        bin_group(sh, a1, b1, c1, m1);
        bin_group(sh, a2, b2, c2, m2);
    }
    if (g < ngroups) {
        float4 a = pos4[3 * g + 0];
        float4 b = pos4[3 * g + 1];
        float4 c = pos4[3 * g + 2];
        float4 m = mass4[g];
        bin_group(sh, a, b, c, m);
    }

    __syncthreads();
    // Flush per-block partials (un-swizzling) to the global accumulator.
    for (int idx = threadIdx.x; idx < NBINS; idx += NTHREADS) {
        float v = sh[idx];
        if (v != 0.0f) {
            int i = idx >> 6;
            int j = (idx & 63) ^ (i & 63);
            atomicAdd(&g_hist[(i << 6) + j], v);
        }
    }

    __threadfence();
    if (threadIdx.x == 0) {
        unsigned int t = atomicAdd(&g_ticket, 1u);
        s_is_last = (t == (unsigned int)(gridDim.x - 1));
    }
    __syncthreads();

    if (s_is_last) {
        const float DRf = 0.15625f;
        const float DZf = 0.0625f;
        const float PIf = 3.14159265358979f;
        for (int idx = threadIdx.x; idx < NBINS; idx += NTHREADS) {
            float v = atomicExch(&g_hist[idx], 0.0f);   // coherent read + reset for next replay
            int i = idx >> 6;
            float r0 = (float)i * DRf;
            float r1 = (float)(i + 1) * DRf;
            float vol = PIf * (r1 * r1 - r0 * r0) * DZf;
            out[idx] = v / vol;
        }
        if (threadIdx.x == 0) atomicExch(&g_ticket, 0u);
    }
}

extern "C" void kernel_launch(void* const* d_in, const int* in_sizes, int n_in,
                              void* d_out, int out_size) {
    const float4* pos4 = (const float4*)d_in[0];   // positions [N,3] float32
    const float4* mass4 = (const float4*)d_in[1];  // masses [N] float32
    int n = in_sizes[1];                           // N points (2^24)
    int ngroups = n / 4;

    fused_hist_kernel<<<NBLOCKS, NTHREADS>>>(pos4, mass4, ngroups, (float*)d_out);
}

// round 4
// speedup vs baseline: 1.0285x; 1.0285x over previous
#include <cuda_runtime.h>

#define R_BINS 64
#define Z_BINS 64
#define NBINS (R_BINS * Z_BINS)
#define NBLOCKS (148 * 4)
#define NTHREADS 512

__device__ float g_hist[NBINS];          // zero at module load; kernel leaves it zeroed
__device__ unsigned int g_ticket;        // zero at module load; kernel resets it

// Swizzled shared index: bank = (j ^ (i&63)) % 32 decorrelates the z-hot banks
// across different r-bins. Bijective per i; un-swizzled at flush.
static __device__ __forceinline__ void bin_point(float* sh, float x, float y, float z, float m) {
    const float DRf = 0.15625f;          // exact in fp32
    const float INV_DR = 6.4f;           // inexact; fixed up against exact edges
    const float Z_MINf = -2.0f;
    const float INV_DZ = 16.0f;          // exact, multiply == reference divide
    float r2 = x * x + y * y;
    // Approx sqrt: 1 MUFU.RSQ + 1 FMUL (vs multi-instr IEEE sqrt subroutine).
    // ~2ulp; only boundary-sliver points can shift one bin -> noise at 1e-3 rel_err.
    float r = (r2 > 0.0f) ? r2 * rsqrtf(r2) : 0.0f;
    int i = (int)(r * INV_DR);           // r >= 0 -> trunc == floor
    if (r < (float)i * DRf) --i;         // exact-edge fixup (edges i*DR exact in fp32)
    else if (r >= (float)(i + 1) * DRf) ++i;
    int j = (int)floorf((z - Z_MINf) * INV_DZ);
    if (i >= 0 && i < R_BINS && j >= 0 && j < Z_BINS) {
        atomicAdd(sh + (i << 6) + (j ^ (i & 63)), m);
    }
}

__global__ void __launch_bounds__(NTHREADS, 4)
fused_hist_kernel(const float4* __restrict__ pos4,
                  const float4* __restrict__ mass4,
                  int ngroups,
                  float* __restrict__ out) {
    __shared__ float sh[NBINS];
    __shared__ int s_is_last;
    for (int i = threadIdx.x; i < NBINS; i += NTHREADS) sh[i] = 0.0f;
    __syncthreads();

    const int stride = gridDim.x * NTHREADS;
    for (int g = blockIdx.x * NTHREADS + threadIdx.x; g < ngroups; g += stride) {
        // 4 points = 12 floats = 3 coalesced float4 loads + 1 float4 of masses
        float4 a = pos4[3 * g + 0];
        float4 b = pos4[3 * g + 1];
        float4 c = pos4[3 * g + 2];
        float4 m = mass4[g];
        bin_point(sh, a.x, a.y, a.z, m.x);
        bin_point(sh, a.w, b.x, b.y, m.y);
        bin_point(sh, b.z, b.w, c.x, m.z);
        bin_point(sh, c.y, c.z, c.w, m.w);
    }

    __syncthreads();
    // Flush per-block partials (un-swizzling) to the global accumulator.
    for (int idx = threadIdx.x; idx < NBINS; idx += NTHREADS) {
        float v = sh[idx];
        if (v != 0.0f) {
            int i = idx >> 6;
            int j = (idx & 63) ^ (i & 63);
            atomicAdd(&g_hist[(i << 6) + j], v);
        }
    }

    __threadfence();
    if (threadIdx.x == 0) {
        unsigned int t = atomicAdd(&g_ticket, 1u);
        s_is_last = (t == (unsigned int)(gridDim.x - 1));
    }
    __syncthreads();

    if (s_is_last) {
        const float DRf = 0.15625f;
        const float DZf = 0.0625f;
        const float PIf = 3.14159265358979f;
        for (int idx = threadIdx.x; idx < NBINS; idx += NTHREADS) {
            float v = atomicExch(&g_hist[idx], 0.0f);   // coherent read + reset for next replay
            int i = idx >> 6;
            float r0 = (float)i * DRf;
            float r1 = (float)(i + 1) * DRf;
            float vol = PIf * (r1 * r1 - r0 * r0) * DZf;
            out[idx] = v / vol;
        }
        if (threadIdx.x == 0) atomicExch(&g_ticket, 0u);
    }
}

extern "C" void kernel_launch(void* const* d_in, const int* in_sizes, int n_in,
                              void* d_out, int out_size) {
    const float4* pos4 = (const float4*)d_in[0];   // positions [N,3] float32
    const float4* mass4 = (const float4*)d_in[1];  // masses [N] float32
    int n = in_sizes[1];                           // N points (2^24)
    int ngroups = n / 4;

    fused_hist_kernel<<<NBLOCKS, NTHREADS>>>(pos4, mass4, ngroups, (float*)d_out);
}